// round 1
// baseline (speedup 1.0000x reference)
#include <cuda_runtime.h>

// Problem constants (fixed-shape dataset)
#define NN 100000   // nodes
#define NE 600000   // edges
#define DD 128      // embed dim
#define NG 1000     // graphs
#define NL 3        // gcn layers

// Scratch (device globals: allocation-free per harness rules)
__device__ float g_bufA[(size_t)NN * DD];   // aggregation accumulator / layer input
__device__ float g_bufB[(size_t)NN * DD];   // transform output (h @ W)
__device__ float g_dinv[NN];                // deg -> rsqrt(deg)
__device__ float g_s[NN];                   // per-node score

typedef unsigned long long u64;

__device__ __forceinline__ u64 fma2(u64 a, u64 b, u64 c) {
    u64 d;
    asm("fma.rn.f32x2 %0, %1, %2, %3;" : "=l"(d) : "l"(a), "l"(b), "l"(c));
    return d;
}
__device__ __forceinline__ u64 pack2(float x, float y) {
    u64 d;
    asm("mov.b64 %0, {%1, %2};" : "=l"(d) : "f"(x), "f"(y));
    return d;
}
__device__ __forceinline__ float2 unpack2(u64 v) {
    float2 r;
    asm("mov.b64 {%0, %1}, %2;" : "=f"(r.x), "=f"(r.y) : "l"(v));
    return r;
}

// ---------------------------------------------------------------------------
// degree / dinv
// ---------------------------------------------------------------------------
__global__ void k_zero(float* p, int n) {
    int i = blockIdx.x * blockDim.x + threadIdx.x;
    if (i < n) p[i] = 0.0f;
}

__global__ void k_count(const int* __restrict__ dst, float* __restrict__ deg) {
    int e = blockIdx.x * blockDim.x + threadIdx.x;
    if (e < NE) atomicAdd(&deg[dst[e]], 1.0f);
}

__global__ void k_dinv(float* __restrict__ dinv) {
    int i = blockIdx.x * blockDim.x + threadIdx.x;
    if (i < NN) dinv[i] = rsqrtf(dinv[i] + 1.0f);
}

// ---------------------------------------------------------------------------
// GEMM: C[n x 128] = (relu?)(A[n x 128]) @ W[128 x 128]
// BM=64, BN=128, BK=16, 256 threads, each thread 8x4 outputs, f32x2 FMA.
// ---------------------------------------------------------------------------
__global__ __launch_bounds__(256) void k_gemm(const float* __restrict__ A,
                                              const float* __restrict__ W,
                                              float* __restrict__ C,
                                              int n, int do_relu)
{
    __shared__ float As[16][64];
    __shared__ float Bs[16][128];

    const int tid = threadIdx.x;
    const int tx = tid & 31;      // 0..31 -> col group of 4
    const int ty = tid >> 5;      // 0..7  -> row group of 8
    const int r0 = blockIdx.x * 64;

    u64 acc[8][2];
#pragma unroll
    for (int i = 0; i < 8; i++) { acc[i][0] = 0ull; acc[i][1] = 0ull; }

    const int arow = tid >> 2;    // 0..63
    const int acol4 = tid & 3;    // 0..3
    const int grow = r0 + arow;

    for (int kk = 0; kk < 128; kk += 16) {
        // A tile: 64 rows x 16 cols (one float4 per thread), optional relu
        float4 av = make_float4(0.f, 0.f, 0.f, 0.f);
        if (grow < n)
            av = *(const float4*)(A + (size_t)grow * DD + kk + acol4 * 4);
        if (do_relu) {
            av.x = fmaxf(av.x, 0.f); av.y = fmaxf(av.y, 0.f);
            av.z = fmaxf(av.z, 0.f); av.w = fmaxf(av.w, 0.f);
        }
        As[acol4 * 4 + 0][arow] = av.x;
        As[acol4 * 4 + 1][arow] = av.y;
        As[acol4 * 4 + 2][arow] = av.z;
        As[acol4 * 4 + 3][arow] = av.w;

        // B tile: 16 rows x 128 cols (two float4 per thread)
#pragma unroll
        for (int p = 0; p < 2; p++) {
            int idx = tid + 256 * p;
            int brow = idx >> 5;
            int bcol = (idx & 31) * 4;
            *(float4*)&Bs[brow][bcol] =
                *(const float4*)(W + (size_t)(kk + brow) * DD + bcol);
        }
        __syncthreads();

#pragma unroll
        for (int k = 0; k < 16; k++) {
            u64 b0 = *(const u64*)&Bs[k][tx * 4];
            u64 b1 = *(const u64*)&Bs[k][tx * 4 + 2];
            float4 a0 = *(const float4*)&As[k][ty * 8];
            float4 a1 = *(const float4*)&As[k][ty * 8 + 4];
            u64 a2;
            a2 = pack2(a0.x, a0.x); acc[0][0] = fma2(a2, b0, acc[0][0]); acc[0][1] = fma2(a2, b1, acc[0][1]);
            a2 = pack2(a0.y, a0.y); acc[1][0] = fma2(a2, b0, acc[1][0]); acc[1][1] = fma2(a2, b1, acc[1][1]);
            a2 = pack2(a0.z, a0.z); acc[2][0] = fma2(a2, b0, acc[2][0]); acc[2][1] = fma2(a2, b1, acc[2][1]);
            a2 = pack2(a0.w, a0.w); acc[3][0] = fma2(a2, b0, acc[3][0]); acc[3][1] = fma2(a2, b1, acc[3][1]);
            a2 = pack2(a1.x, a1.x); acc[4][0] = fma2(a2, b0, acc[4][0]); acc[4][1] = fma2(a2, b1, acc[4][1]);
            a2 = pack2(a1.y, a1.y); acc[5][0] = fma2(a2, b0, acc[5][0]); acc[5][1] = fma2(a2, b1, acc[5][1]);
            a2 = pack2(a1.z, a1.z); acc[6][0] = fma2(a2, b0, acc[6][0]); acc[6][1] = fma2(a2, b1, acc[6][1]);
            a2 = pack2(a1.w, a1.w); acc[7][0] = fma2(a2, b0, acc[7][0]); acc[7][1] = fma2(a2, b1, acc[7][1]);
        }
        __syncthreads();
    }

#pragma unroll
    for (int i = 0; i < 8; i++) {
        int row = r0 + ty * 8 + i;
        if (row < n) {
            float2 lo = unpack2(acc[i][0]);
            float2 hi = unpack2(acc[i][1]);
            *(float4*)(C + (size_t)row * DD + tx * 4) = make_float4(lo.x, lo.y, hi.x, hi.y);
        }
    }
}

// ---------------------------------------------------------------------------
// init accumulator: ACC = T * dinv[node]^2 + bias
// ---------------------------------------------------------------------------
__global__ void k_init(const float* __restrict__ T, const float* __restrict__ dinv,
                       const float* __restrict__ bias, float* __restrict__ ACC)
{
    int idx = blockIdx.x * blockDim.x + threadIdx.x;   // over NN*32 float4 units
    if (idx >= NN * 32) return;
    int node = idx >> 5;
    int c4 = idx & 31;
    float sn = dinv[node]; sn = sn * sn;
    float4 t = *(const float4*)(T + (size_t)idx * 4);
    float4 b = *(const float4*)(bias + c4 * 4);
    float4 o = make_float4(fmaf(t.x, sn, b.x), fmaf(t.y, sn, b.y),
                           fmaf(t.z, sn, b.z), fmaf(t.w, sn, b.w));
    *(float4*)(ACC + (size_t)idx * 4) = o;
}

// ---------------------------------------------------------------------------
// scatter: ACC[dst] += H[src] * (dinv[src]*dinv[dst]), one warp per edge
// ---------------------------------------------------------------------------
__global__ void k_scatter(const float* __restrict__ H, float* __restrict__ ACC,
                          const int* __restrict__ src, const int* __restrict__ dst,
                          const float* __restrict__ dinv)
{
    int g = blockIdx.x * blockDim.x + threadIdx.x;
    int e = g >> 5;
    int lane = g & 31;
    if (e >= NE) return;
    int s = src[e];
    int d = dst[e];
    float en = dinv[s] * dinv[d];
    float4 v = *(const float4*)(H + (size_t)s * DD + lane * 4);
    float* p = ACC + (size_t)d * DD + lane * 4;
    atomicAdd(p + 0, v.x * en);
    atomicAdd(p + 1, v.y * en);
    atomicAdd(p + 2, v.z * en);
    atomicAdd(p + 3, v.w * en);
}

// ---------------------------------------------------------------------------
// fused MLP head: s = relu(h @ W1 + b1) @ w2 + b2, mask, per-node score
// Same tiling as k_gemm; epilogue does relu/dot/warp-reduce instead of store.
// ---------------------------------------------------------------------------
__global__ __launch_bounds__(256) void k_mlp(const float* __restrict__ A,
                                             const float* __restrict__ W1,
                                             const float* __restrict__ b1,
                                             const float* __restrict__ w2,
                                             const float* __restrict__ b2p,
                                             const int* __restrict__ mask,
                                             float* __restrict__ S, int n)
{
    __shared__ float As[16][64];
    __shared__ float Bs[16][128];

    const int tid = threadIdx.x;
    const int tx = tid & 31;
    const int ty = tid >> 5;
    const int r0 = blockIdx.x * 64;

    u64 acc[8][2];
#pragma unroll
    for (int i = 0; i < 8; i++) { acc[i][0] = 0ull; acc[i][1] = 0ull; }

    const int arow = tid >> 2;
    const int acol4 = tid & 3;
    const int grow = r0 + arow;

    for (int kk = 0; kk < 128; kk += 16) {
        float4 av = make_float4(0.f, 0.f, 0.f, 0.f);
        if (grow < n)
            av = *(const float4*)(A + (size_t)grow * DD + kk + acol4 * 4);
        As[acol4 * 4 + 0][arow] = av.x;
        As[acol4 * 4 + 1][arow] = av.y;
        As[acol4 * 4 + 2][arow] = av.z;
        As[acol4 * 4 + 3][arow] = av.w;
#pragma unroll
        for (int p = 0; p < 2; p++) {
            int idx = tid + 256 * p;
            int brow = idx >> 5;
            int bcol = (idx & 31) * 4;
            *(float4*)&Bs[brow][bcol] =
                *(const float4*)(W1 + (size_t)(kk + brow) * DD + bcol);
        }
        __syncthreads();
#pragma unroll
        for (int k = 0; k < 16; k++) {
            u64 b0 = *(const u64*)&Bs[k][tx * 4];
            u64 b1v = *(const u64*)&Bs[k][tx * 4 + 2];
            float4 a0 = *(const float4*)&As[k][ty * 8];
            float4 a1 = *(const float4*)&As[k][ty * 8 + 4];
            u64 a2;
            a2 = pack2(a0.x, a0.x); acc[0][0] = fma2(a2, b0, acc[0][0]); acc[0][1] = fma2(a2, b1v, acc[0][1]);
            a2 = pack2(a0.y, a0.y); acc[1][0] = fma2(a2, b0, acc[1][0]); acc[1][1] = fma2(a2, b1v, acc[1][1]);
            a2 = pack2(a0.z, a0.z); acc[2][0] = fma2(a2, b0, acc[2][0]); acc[2][1] = fma2(a2, b1v, acc[2][1]);
            a2 = pack2(a0.w, a0.w); acc[3][0] = fma2(a2, b0, acc[3][0]); acc[3][1] = fma2(a2, b1v, acc[3][1]);
            a2 = pack2(a1.x, a1.x); acc[4][0] = fma2(a2, b0, acc[4][0]); acc[4][1] = fma2(a2, b1v, acc[4][1]);
            a2 = pack2(a1.y, a1.y); acc[5][0] = fma2(a2, b0, acc[5][0]); acc[5][1] = fma2(a2, b1v, acc[5][1]);
            a2 = pack2(a1.z, a1.z); acc[6][0] = fma2(a2, b0, acc[6][0]); acc[6][1] = fma2(a2, b1v, acc[6][1]);
            a2 = pack2(a1.w, a1.w); acc[7][0] = fma2(a2, b0, acc[7][0]); acc[7][1] = fma2(a2, b1v, acc[7][1]);
        }
        __syncthreads();
    }

    // epilogue: relu + bias + dot with w2, warp-reduce across the 32 col-lanes
    float bv0 = b1[tx * 4 + 0], bv1 = b1[tx * 4 + 1], bv2 = b1[tx * 4 + 2], bv3 = b1[tx * 4 + 3];
    float wv0 = w2[tx * 4 + 0], wv1 = w2[tx * 4 + 1], wv2 = w2[tx * 4 + 2], wv3 = w2[tx * 4 + 3];
    float b2 = b2p[0];

#pragma unroll
    for (int i = 0; i < 8; i++) {
        float2 lo = unpack2(acc[i][0]);
        float2 hi = unpack2(acc[i][1]);
        float t = fmaxf(lo.x + bv0, 0.f) * wv0 + fmaxf(lo.y + bv1, 0.f) * wv1 +
                  fmaxf(hi.x + bv2, 0.f) * wv2 + fmaxf(hi.y + bv3, 0.f) * wv3;
#pragma unroll
        for (int off = 16; off > 0; off >>= 1)
            t += __shfl_xor_sync(0xffffffffu, t, off);
        if (tx == 0) {
            int row = r0 + ty * 8 + i;
            if (row < n) {
                float sv = t + b2;
                if (mask[row] == 0) sv = -1e9f;
                S[row] = sv;
            }
        }
    }
}

// ---------------------------------------------------------------------------
// per-graph segment softmax (batch is sorted) — one block per graph
// ---------------------------------------------------------------------------
__device__ __forceinline__ int lower_bound(const int* __restrict__ a, int n, int v) {
    int lo = 0, hi = n;
    while (lo < hi) {
        int mid = (lo + hi) >> 1;
        if (a[mid] < v) lo = mid + 1; else hi = mid;
    }
    return lo;
}

__global__ __launch_bounds__(256) void k_softmax(const float* __restrict__ S,
                                                 const int* __restrict__ batch,
                                                 float* __restrict__ out)
{
    __shared__ float red[256];
    __shared__ int seg[2];
    const int tid = threadIdx.x;
    const int g = blockIdx.x;

    if (tid == 0) {
        seg[0] = lower_bound(batch, NN, g);
        seg[1] = lower_bound(batch, NN, g + 1);
    }
    __syncthreads();
    const int start = seg[0], end = seg[1];
    if (start >= end) return;

    // max
    float m = -3.4e38f;
    for (int i = start + tid; i < end; i += 256) m = fmaxf(m, S[i]);
    red[tid] = m;
    __syncthreads();
    for (int o = 128; o > 0; o >>= 1) {
        if (tid < o) red[tid] = fmaxf(red[tid], red[tid + o]);
        __syncthreads();
    }
    m = red[0];
    __syncthreads();

    // sum exp
    float z = 0.f;
    for (int i = start + tid; i < end; i += 256) z += expf(S[i] - m);
    red[tid] = z;
    __syncthreads();
    for (int o = 128; o > 0; o >>= 1) {
        if (tid < o) red[tid] += red[tid + o];
        __syncthreads();
    }
    z = red[0];

    float inv = 1.0f / z;
    for (int i = start + tid; i < end; i += 256) out[i] = expf(S[i] - m) * inv;
}

// ---------------------------------------------------------------------------
// launch
// ---------------------------------------------------------------------------
extern "C" void kernel_launch(void* const* d_in, const int* in_sizes, int n_in,
                              void* d_out, int out_size)
{
    const float* x       = (const float*)d_in[0];
    const int*   eidx    = (const int*)d_in[1];
    const int*   batch   = (const int*)d_in[2];
    const int*   mask    = (const int*)d_in[3];
    const float* gcn_w   = (const float*)d_in[4];   // [L,128,128]
    const float* gcn_b   = (const float*)d_in[5];   // [L,128]
    const float* lin1_w  = (const float*)d_in[6];   // [128,128]
    const float* lin1_b  = (const float*)d_in[7];   // [128]
    const float* lin2_w  = (const float*)d_in[8];   // [128]
    const float* lin2_b  = (const float*)d_in[9];   // scalar
    float* out = (float*)d_out;

    const int* src = eidx;
    const int* dst = eidx + NE;

    float *bufA, *bufB, *dinv, *sbuf;
    cudaGetSymbolAddress((void**)&bufA, g_bufA);
    cudaGetSymbolAddress((void**)&bufB, g_bufB);
    cudaGetSymbolAddress((void**)&dinv, g_dinv);
    cudaGetSymbolAddress((void**)&sbuf, g_s);

    // degree -> dinv
    k_zero<<<(NN + 255) / 256, 256>>>(dinv, NN);
    k_count<<<(NE + 255) / 256, 256>>>(dst, dinv);
    k_dinv<<<(NN + 255) / 256, 256>>>(dinv);

    const int gemm_blocks = (NN + 63) / 64;
    const int init_blocks = (NN * 32 + 255) / 256;
    const int scat_blocks = (NE * 32 + 255) / 256;

    // GCN layers
    const float* in_ptr = x;
    for (int l = 0; l < NL; l++) {
        k_gemm<<<gemm_blocks, 256>>>(in_ptr, gcn_w + (size_t)l * DD * DD, bufB, NN,
                                     (l > 0) ? 1 : 0);
        k_init<<<init_blocks, 256>>>(bufB, dinv, gcn_b + (size_t)l * DD, bufA);
        k_scatter<<<scat_blocks, 256>>>(bufB, bufA, src, dst, dinv);
        in_ptr = bufA;  // relu (for l<2) is applied on load in the next k_gemm
    }

    // MLP head -> per-node score (mask folded in)
    k_mlp<<<gemm_blocks, 256>>>(bufA, lin1_w, lin1_b, lin2_w, lin2_b, mask, sbuf, NN);

    // per-graph softmax
    k_softmax<<<NG, 256>>>(sbuf, batch, out);
}

// round 2
// speedup vs baseline: 1.7240x; 1.7240x over previous
#include <cuda_runtime.h>

// Problem constants (fixed-shape dataset)
#define NN 100000   // nodes
#define NE 600000   // edges
#define DD 128      // embed dim
#define NG 1000     // graphs
#define NL 3        // gcn layers

// Scratch (device globals: allocation-free per harness rules)
__device__ float g_bufA[(size_t)NN * DD];   // aggregated layer output
__device__ float g_bufB[(size_t)NN * DD];   // transform output (h @ W)
__device__ float g_dinv[NN];                // rsqrt(deg+1)
__device__ float g_s[NN];                   // per-node score
__device__ int   g_counts[NN];              // in-degree histogram
__device__ int   g_cursor[NN];              // placement cursors
__device__ int   g_offs[NN + 1];            // CSR offsets
__device__ int2  g_sorted[NE];              // (src, bitcast(edge_norm)) grouped by dst

typedef unsigned long long u64;

__device__ __forceinline__ u64 fma2(u64 a, u64 b, u64 c) {
    u64 d;
    asm("fma.rn.f32x2 %0, %1, %2, %3;" : "=l"(d) : "l"(a), "l"(b), "l"(c));
    return d;
}
__device__ __forceinline__ u64 pack2(float x, float y) {
    u64 d;
    asm("mov.b64 %0, {%1, %2};" : "=l"(d) : "f"(x), "f"(y));
    return d;
}
__device__ __forceinline__ float2 unpack2(u64 v) {
    float2 r;
    asm("mov.b64 {%0, %1}, %2;" : "=f"(r.x), "=f"(r.y) : "l"(v));
    return r;
}

// ---------------------------------------------------------------------------
// CSR build: histogram -> scan -> place
// ---------------------------------------------------------------------------
__global__ void k_zero_int(int* p, int n) {
    int i = blockIdx.x * blockDim.x + threadIdx.x;
    if (i < n) p[i] = 0;
}

__global__ void k_hist(const int* __restrict__ dst, int* __restrict__ counts) {
    int e = blockIdx.x * blockDim.x + threadIdx.x;
    if (e < NE) atomicAdd(&counts[dst[e]], 1);
}

__global__ void k_dinv(const int* __restrict__ counts, float* __restrict__ dinv) {
    int i = blockIdx.x * blockDim.x + threadIdx.x;
    if (i < NN) dinv[i] = rsqrtf((float)counts[i] + 1.0f);
}

// single-block exclusive scan over counts -> offs, cursor
__global__ __launch_bounds__(1024) void k_scan(const int* __restrict__ counts,
                                               int* __restrict__ offs,
                                               int* __restrict__ cursor)
{
    __shared__ int warp_sums[32];
    const int tid = threadIdx.x;
    const int lane = tid & 31;
    const int wid = tid >> 5;
    int carry = 0;

    for (int base = 0; base < NN; base += 1024) {
        int i = base + tid;
        int v = (i < NN) ? counts[i] : 0;
        // inclusive warp scan
        int x = v;
#pragma unroll
        for (int o = 1; o < 32; o <<= 1) {
            int y = __shfl_up_sync(0xffffffffu, x, o);
            if (lane >= o) x += y;
        }
        if (lane == 31) warp_sums[wid] = x;
        __syncthreads();
        if (wid == 0) {
            int s = warp_sums[lane];
#pragma unroll
            for (int o = 1; o < 32; o <<= 1) {
                int y = __shfl_up_sync(0xffffffffu, s, o);
                if (lane >= o) s += y;
            }
            warp_sums[lane] = s;
        }
        __syncthreads();
        int wpre = (wid > 0) ? warp_sums[wid - 1] : 0;
        int excl = carry + wpre + x - v;
        if (i < NN) { offs[i] = excl; cursor[i] = excl; }
        int total = warp_sums[31];
        __syncthreads();   // protect warp_sums before next iteration
        carry += total;
    }
    if (tid == 0) offs[NN] = carry;
}

__global__ void k_place(const int* __restrict__ src, const int* __restrict__ dst,
                        const float* __restrict__ dinv,
                        int* __restrict__ cursor, int2* __restrict__ sorted)
{
    int e = blockIdx.x * blockDim.x + threadIdx.x;
    if (e >= NE) return;
    int s = src[e];
    int d = dst[e];
    float en = dinv[s] * dinv[d];
    int pos = atomicAdd(&cursor[d], 1);
    sorted[pos] = make_int2(s, __float_as_int(en));
}

// ---------------------------------------------------------------------------
// GEMM: C[n x 128] = A[n x 128] @ W[128 x 128]
// BM=64, BN=128, BK=16, 256 threads, each thread 8x4 outputs, f32x2 FMA.
// ---------------------------------------------------------------------------
__global__ __launch_bounds__(256) void k_gemm(const float* __restrict__ A,
                                              const float* __restrict__ W,
                                              float* __restrict__ C, int n)
{
    __shared__ float As[16][64];
    __shared__ float Bs[16][128];

    const int tid = threadIdx.x;
    const int tx = tid & 31;
    const int ty = tid >> 5;
    const int r0 = blockIdx.x * 64;

    u64 acc[8][2];
#pragma unroll
    for (int i = 0; i < 8; i++) { acc[i][0] = 0ull; acc[i][1] = 0ull; }

    const int arow = tid >> 2;
    const int acol4 = tid & 3;
    const int grow = r0 + arow;

    for (int kk = 0; kk < 128; kk += 16) {
        float4 av = make_float4(0.f, 0.f, 0.f, 0.f);
        if (grow < n)
            av = *(const float4*)(A + (size_t)grow * DD + kk + acol4 * 4);
        As[acol4 * 4 + 0][arow] = av.x;
        As[acol4 * 4 + 1][arow] = av.y;
        As[acol4 * 4 + 2][arow] = av.z;
        As[acol4 * 4 + 3][arow] = av.w;

#pragma unroll
        for (int p = 0; p < 2; p++) {
            int idx = tid + 256 * p;
            int brow = idx >> 5;
            int bcol = (idx & 31) * 4;
            *(float4*)&Bs[brow][bcol] =
                *(const float4*)(W + (size_t)(kk + brow) * DD + bcol);
        }
        __syncthreads();

#pragma unroll
        for (int k = 0; k < 16; k++) {
            u64 b0 = *(const u64*)&Bs[k][tx * 4];
            u64 b1 = *(const u64*)&Bs[k][tx * 4 + 2];
            float4 a0 = *(const float4*)&As[k][ty * 8];
            float4 a1 = *(const float4*)&As[k][ty * 8 + 4];
            u64 a2;
            a2 = pack2(a0.x, a0.x); acc[0][0] = fma2(a2, b0, acc[0][0]); acc[0][1] = fma2(a2, b1, acc[0][1]);
            a2 = pack2(a0.y, a0.y); acc[1][0] = fma2(a2, b0, acc[1][0]); acc[1][1] = fma2(a2, b1, acc[1][1]);
            a2 = pack2(a0.z, a0.z); acc[2][0] = fma2(a2, b0, acc[2][0]); acc[2][1] = fma2(a2, b1, acc[2][1]);
            a2 = pack2(a0.w, a0.w); acc[3][0] = fma2(a2, b0, acc[3][0]); acc[3][1] = fma2(a2, b1, acc[3][1]);
            a2 = pack2(a1.x, a1.x); acc[4][0] = fma2(a2, b0, acc[4][0]); acc[4][1] = fma2(a2, b1, acc[4][1]);
            a2 = pack2(a1.y, a1.y); acc[5][0] = fma2(a2, b0, acc[5][0]); acc[5][1] = fma2(a2, b1, acc[5][1]);
            a2 = pack2(a1.z, a1.z); acc[6][0] = fma2(a2, b0, acc[6][0]); acc[6][1] = fma2(a2, b1, acc[6][1]);
            a2 = pack2(a1.w, a1.w); acc[7][0] = fma2(a2, b0, acc[7][0]); acc[7][1] = fma2(a2, b1, acc[7][1]);
        }
        __syncthreads();
    }

#pragma unroll
    for (int i = 0; i < 8; i++) {
        int row = r0 + ty * 8 + i;
        if (row < n) {
            float2 lo = unpack2(acc[i][0]);
            float2 hi = unpack2(acc[i][1]);
            *(float4*)(C + (size_t)row * DD + tx * 4) = make_float4(lo.x, lo.y, hi.x, hi.y);
        }
    }
}

// ---------------------------------------------------------------------------
// gather-aggregate: one warp per node
// OUT[i] = relu?( H[i]*dinv[i]^2 + bias + sum_{e in CSR[i]} H[src_e]*en_e )
// ---------------------------------------------------------------------------
__global__ __launch_bounds__(256) void k_aggregate(const float* __restrict__ H,
                                                   const int* __restrict__ offs,
                                                   const int2* __restrict__ sorted,
                                                   const float* __restrict__ dinv,
                                                   const float* __restrict__ bias,
                                                   float* __restrict__ OUT,
                                                   int do_relu)
{
    int g = blockIdx.x * blockDim.x + threadIdx.x;
    int i = g >> 5;
    int lane = g & 31;
    if (i >= NN) return;

    float di = dinv[i];
    float sn = di * di;

    float4 h = *(const float4*)(H + (size_t)i * DD + lane * 4);
    float4 b = *(const float4*)(bias + lane * 4);
    float4 acc = make_float4(fmaf(h.x, sn, b.x), fmaf(h.y, sn, b.y),
                             fmaf(h.z, sn, b.z), fmaf(h.w, sn, b.w));

    int e0 = offs[i];
    int e1 = offs[i + 1];
    for (int e = e0; e < e1; e++) {
        int2 p = sorted[e];                       // uniform across warp (broadcast)
        float en = __int_as_float(p.y);
        float4 v = *(const float4*)(H + (size_t)p.x * DD + lane * 4);
        acc.x = fmaf(v.x, en, acc.x);
        acc.y = fmaf(v.y, en, acc.y);
        acc.z = fmaf(v.z, en, acc.z);
        acc.w = fmaf(v.w, en, acc.w);
    }

    if (do_relu) {
        acc.x = fmaxf(acc.x, 0.f); acc.y = fmaxf(acc.y, 0.f);
        acc.z = fmaxf(acc.z, 0.f); acc.w = fmaxf(acc.w, 0.f);
    }
    *(float4*)(OUT + (size_t)i * DD + lane * 4) = acc;
}

// ---------------------------------------------------------------------------
// fused MLP head: s = relu(h @ W1 + b1) @ w2 + b2, mask -> per-node score
// ---------------------------------------------------------------------------
__global__ __launch_bounds__(256) void k_mlp(const float* __restrict__ A,
                                             const float* __restrict__ W1,
                                             const float* __restrict__ b1,
                                             const float* __restrict__ w2,
                                             const float* __restrict__ b2p,
                                             const int* __restrict__ mask,
                                             float* __restrict__ S, int n)
{
    __shared__ float As[16][64];
    __shared__ float Bs[16][128];

    const int tid = threadIdx.x;
    const int tx = tid & 31;
    const int ty = tid >> 5;
    const int r0 = blockIdx.x * 64;

    u64 acc[8][2];
#pragma unroll
    for (int i = 0; i < 8; i++) { acc[i][0] = 0ull; acc[i][1] = 0ull; }

    const int arow = tid >> 2;
    const int acol4 = tid & 3;
    const int grow = r0 + arow;

    for (int kk = 0; kk < 128; kk += 16) {
        float4 av = make_float4(0.f, 0.f, 0.f, 0.f);
        if (grow < n)
            av = *(const float4*)(A + (size_t)grow * DD + kk + acol4 * 4);
        As[acol4 * 4 + 0][arow] = av.x;
        As[acol4 * 4 + 1][arow] = av.y;
        As[acol4 * 4 + 2][arow] = av.z;
        As[acol4 * 4 + 3][arow] = av.w;
#pragma unroll
        for (int p = 0; p < 2; p++) {
            int idx = tid + 256 * p;
            int brow = idx >> 5;
            int bcol = (idx & 31) * 4;
            *(float4*)&Bs[brow][bcol] =
                *(const float4*)(W1 + (size_t)(kk + brow) * DD + bcol);
        }
        __syncthreads();
#pragma unroll
        for (int k = 0; k < 16; k++) {
            u64 b0 = *(const u64*)&Bs[k][tx * 4];
            u64 b1v = *(const u64*)&Bs[k][tx * 4 + 2];
            float4 a0 = *(const float4*)&As[k][ty * 8];
            float4 a1 = *(const float4*)&As[k][ty * 8 + 4];
            u64 a2;
            a2 = pack2(a0.x, a0.x); acc[0][0] = fma2(a2, b0, acc[0][0]); acc[0][1] = fma2(a2, b1v, acc[0][1]);
            a2 = pack2(a0.y, a0.y); acc[1][0] = fma2(a2, b0, acc[1][0]); acc[1][1] = fma2(a2, b1v, acc[1][1]);
            a2 = pack2(a0.z, a0.z); acc[2][0] = fma2(a2, b0, acc[2][0]); acc[2][1] = fma2(a2, b1v, acc[2][1]);
            a2 = pack2(a0.w, a0.w); acc[3][0] = fma2(a2, b0, acc[3][0]); acc[3][1] = fma2(a2, b1v, acc[3][1]);
            a2 = pack2(a1.x, a1.x); acc[4][0] = fma2(a2, b0, acc[4][0]); acc[4][1] = fma2(a2, b1v, acc[4][1]);
            a2 = pack2(a1.y, a1.y); acc[5][0] = fma2(a2, b0, acc[5][0]); acc[5][1] = fma2(a2, b1v, acc[5][1]);
            a2 = pack2(a1.z, a1.z); acc[6][0] = fma2(a2, b0, acc[6][0]); acc[6][1] = fma2(a2, b1v, acc[6][1]);
            a2 = pack2(a1.w, a1.w); acc[7][0] = fma2(a2, b0, acc[7][0]); acc[7][1] = fma2(a2, b1v, acc[7][1]);
        }
        __syncthreads();
    }

    float bv0 = b1[tx * 4 + 0], bv1 = b1[tx * 4 + 1], bv2 = b1[tx * 4 + 2], bv3 = b1[tx * 4 + 3];
    float wv0 = w2[tx * 4 + 0], wv1 = w2[tx * 4 + 1], wv2 = w2[tx * 4 + 2], wv3 = w2[tx * 4 + 3];
    float b2 = b2p[0];

#pragma unroll
    for (int i = 0; i < 8; i++) {
        float2 lo = unpack2(acc[i][0]);
        float2 hi = unpack2(acc[i][1]);
        float t = fmaxf(lo.x + bv0, 0.f) * wv0 + fmaxf(lo.y + bv1, 0.f) * wv1 +
                  fmaxf(hi.x + bv2, 0.f) * wv2 + fmaxf(hi.y + bv3, 0.f) * wv3;
#pragma unroll
        for (int off = 16; off > 0; off >>= 1)
            t += __shfl_xor_sync(0xffffffffu, t, off);
        if (tx == 0) {
            int row = r0 + ty * 8 + i;
            if (row < n) {
                float sv = t + b2;
                if (mask[row] == 0) sv = -1e9f;
                S[row] = sv;
            }
        }
    }
}

// ---------------------------------------------------------------------------
// per-graph segment softmax (batch is sorted) — one block per graph
// ---------------------------------------------------------------------------
__device__ __forceinline__ int lower_bound(const int* __restrict__ a, int n, int v) {
    int lo = 0, hi = n;
    while (lo < hi) {
        int mid = (lo + hi) >> 1;
        if (a[mid] < v) lo = mid + 1; else hi = mid;
    }
    return lo;
}

__global__ __launch_bounds__(256) void k_softmax(const float* __restrict__ S,
                                                 const int* __restrict__ batch,
                                                 float* __restrict__ out)
{
    __shared__ float red[256];
    __shared__ int seg[2];
    const int tid = threadIdx.x;
    const int g = blockIdx.x;

    if (tid == 0) {
        seg[0] = lower_bound(batch, NN, g);
        seg[1] = lower_bound(batch, NN, g + 1);
    }
    __syncthreads();
    const int start = seg[0], end = seg[1];
    if (start >= end) return;

    float m = -3.4e38f;
    for (int i = start + tid; i < end; i += 256) m = fmaxf(m, S[i]);
    red[tid] = m;
    __syncthreads();
    for (int o = 128; o > 0; o >>= 1) {
        if (tid < o) red[tid] = fmaxf(red[tid], red[tid + o]);
        __syncthreads();
    }
    m = red[0];
    __syncthreads();

    float z = 0.f;
    for (int i = start + tid; i < end; i += 256) z += expf(S[i] - m);
    red[tid] = z;
    __syncthreads();
    for (int o = 128; o > 0; o >>= 1) {
        if (tid < o) red[tid] += red[tid + o];
        __syncthreads();
    }
    z = red[0];

    float inv = 1.0f / z;
    for (int i = start + tid; i < end; i += 256) out[i] = expf(S[i] - m) * inv;
}

// ---------------------------------------------------------------------------
// launch
// ---------------------------------------------------------------------------
extern "C" void kernel_launch(void* const* d_in, const int* in_sizes, int n_in,
                              void* d_out, int out_size)
{
    const float* x       = (const float*)d_in[0];
    const int*   eidx    = (const int*)d_in[1];
    const int*   batch   = (const int*)d_in[2];
    const int*   mask    = (const int*)d_in[3];
    const float* gcn_w   = (const float*)d_in[4];
    const float* gcn_b   = (const float*)d_in[5];
    const float* lin1_w  = (const float*)d_in[6];
    const float* lin1_b  = (const float*)d_in[7];
    const float* lin2_w  = (const float*)d_in[8];
    const float* lin2_b  = (const float*)d_in[9];
    float* out = (float*)d_out;

    const int* src = eidx;
    const int* dst = eidx + NE;

    float *bufA, *bufB, *dinv, *sbuf;
    int *counts, *cursor, *offs;
    int2 *sorted;
    cudaGetSymbolAddress((void**)&bufA, g_bufA);
    cudaGetSymbolAddress((void**)&bufB, g_bufB);
    cudaGetSymbolAddress((void**)&dinv, g_dinv);
    cudaGetSymbolAddress((void**)&sbuf, g_s);
    cudaGetSymbolAddress((void**)&counts, g_counts);
    cudaGetSymbolAddress((void**)&cursor, g_cursor);
    cudaGetSymbolAddress((void**)&offs, g_offs);
    cudaGetSymbolAddress((void**)&sorted, g_sorted);

    // CSR build (once per launch)
    k_zero_int<<<(NN + 255) / 256, 256>>>(counts, NN);
    k_hist<<<(NE + 255) / 256, 256>>>(dst, counts);
    k_dinv<<<(NN + 255) / 256, 256>>>(counts, dinv);
    k_scan<<<1, 1024>>>(counts, offs, cursor);
    k_place<<<(NE + 255) / 256, 256>>>(src, dst, dinv, cursor, sorted);

    const int gemm_blocks = (NN + 63) / 64;
    const int agg_blocks = (NN * 32 + 255) / 256;

    // GCN layers: gemm -> gather-aggregate (self-loop + bias + relu fused)
    const float* in_ptr = x;
    for (int l = 0; l < NL; l++) {
        k_gemm<<<gemm_blocks, 256>>>(in_ptr, gcn_w + (size_t)l * DD * DD, bufB, NN);
        k_aggregate<<<agg_blocks, 256>>>(bufB, offs, sorted, dinv,
                                         gcn_b + (size_t)l * DD, bufA,
                                         (l < NL - 1) ? 1 : 0);
        in_ptr = bufA;
    }

    // MLP head -> per-node score (mask folded in)
    k_mlp<<<gemm_blocks, 256>>>(bufA, lin1_w, lin1_b, lin2_w, lin2_b, mask, sbuf, NN);

    // per-graph softmax
    k_softmax<<<NG, 256>>>(sbuf, batch, out);
}